// round 1
// baseline (speedup 1.0000x reference)
#include <cuda_runtime.h>

// x: [8,16,256,256] f32  ->  out: [8,64,256,256] f32
// Per (b,c) image: 4 feature planes (contrast, energy, entropy, homogeneity),
// output channel = (b*16 + c)*4 + f.

#define TW 32
#define TH 8
#define SW (TW + 2)   // 34
#define SH (TH + 2)   // 10
#define HW 65536      // 256*256

__global__ __launch_bounds__(256) void glcm_martingale_kernel(
    const float* __restrict__ x, float* __restrict__ out)
{
    __shared__ float xs[SH][SW];
    __shared__ float ts[SH][SW];

    const int img = blockIdx.z;                 // 0..127 = b*16+c
    const int h0  = blockIdx.y * TH - 1;
    const int w0  = blockIdx.x * TW - 1;
    const float* __restrict__ xin = x + (size_t)img * HW;

    // ---- cooperative tile load + per-element t = v*log(v+eps) ----
    const int tid = threadIdx.y * TW + threadIdx.x;
    #pragma unroll
    for (int i = tid; i < SH * SW; i += 256) {
        const int r = i / SW, c = i % SW;
        const int gh = h0 + r, gw = w0 + c;
        float v = 0.0f;
        if ((unsigned)gh < 256u && (unsigned)gw < 256u)
            v = xin[gh * 256 + gw];
        xs[r][c] = v;
        ts[r][c] = v * __logf(v + 1e-6f);   // 0*log(eps)=0 matches zero-pad
    }
    __syncthreads();

    const int ty = threadIdx.y, tx = threadIdx.x;

    float p[9];
    float s1 = 0.0f, s2 = 0.0f, st = 0.0f;
    #pragma unroll
    for (int i = 0; i < 3; i++) {
        #pragma unroll
        for (int j = 0; j < 3; j++) {
            const float v = xs[ty + i][tx + j];
            p[i * 3 + j] = v;
            s1 += v;
            s2 = fmaf(v, v, s2);
            st += ts[ty + i][tx + j];
        }
    }

    const float inv9 = 1.0f / 9.0f;
    const float mean = s1 * inv9;

    // sum of squared deviations: s2 - s1^2/9
    float ss = fmaf(-s1, mean, s2);
    ss = fmaxf(ss, 0.0f);

    const float stdv = sqrtf(ss * 0.125f) + 1e-6f;   // ddof=1 -> /8

    const float contrast = __fdividef(ss * inv9, stdv * stdv);
    const float energy   = s2 * inv9;
    const float entropy  = -st * inv9;

    float sa = 0.0f;
    #pragma unroll
    for (int k = 0; k < 9; k++)
        sa += fabsf(p[k] - mean);
    const float homog = __fdividef(1.0f, fmaf(sa, inv9, 1.0f));

    // M = (feat + 1e-6) * exp(-0.5)
    const float E = 0.60653065971263342f;

    const int h = blockIdx.y * TH + ty;
    const int w = blockIdx.x * TW + tx;
    float* __restrict__ o = out + (size_t)img * 4 * HW + h * 256 + w;

    o[0 * HW] = (contrast + 1e-6f) * E;
    o[1 * HW] = (energy   + 1e-6f) * E;
    o[2 * HW] = (entropy  + 1e-6f) * E;
    o[3 * HW] = (homog    + 1e-6f) * E;
}

extern "C" void kernel_launch(void* const* d_in, const int* in_sizes, int n_in,
                              void* d_out, int out_size)
{
    const float* x = (const float*)d_in[0];
    float* out = (float*)d_out;
    (void)in_sizes; (void)n_in; (void)out_size;

    dim3 block(TW, TH);
    dim3 grid(256 / TW, 256 / TH, 8 * 16);
    glcm_martingale_kernel<<<grid, block>>>(x, out);
}

// round 2
// speedup vs baseline: 1.4135x; 1.4135x over previous
#include <cuda_runtime.h>

// x: [8,16,256,256] f32  ->  out: [8,64,256,256] f32
// Features per (b,c): contrast, energy, entropy, homogeneity at out channel (b*16+c)*4+f.
// Block: 32x8 threads, each thread computes 4 horizontal pixels -> tile 128x8.

#define TW 128          // tile width in pixels
#define TH 8            // tile height
#define SWU 130         // used smem cols (w-1 .. w+128)
#define SWA 132         // allocated (16B-aligned rows, slack for vector loads)
#define SH  10          // tile rows + halo
#define HW 65536        // 256*256

__global__ __launch_bounds__(256) void glcm_martingale_kernel(
    const float* __restrict__ x, float* __restrict__ out)
{
    __shared__ float xs[SH][SWA];
    __shared__ float ts[SH][SWA];

    const int img = blockIdx.z;                 // b*16+c
    const int h0  = blockIdx.y * TH;            // tile origin (pixel space)
    const int w0  = blockIdx.x * TW;
    const float* __restrict__ xin = x + (size_t)img * HW;

    // ---- cooperative tile load: rows h0-1..h0+8, cols w0-1..w0+128 ----
    const int tid = threadIdx.y * 32 + threadIdx.x;
    for (int idx = tid; idx < SH * SWU; idx += 256) {
        const int r = idx / SWU;
        const int c = idx - r * SWU;
        const int gh = h0 - 1 + r;
        const int gw = w0 - 1 + c;
        float v = 0.0f;
        if ((unsigned)gh < 256u && (unsigned)gw < 256u)
            v = xin[gh * 256 + gw];
        xs[r][c] = v;
        ts[r][c] = v * __logf(v + 1e-6f);   // 0*log(eps) = 0 matches zero-pad
    }
    __syncthreads();

    const int ty = threadIdx.y, tx = threadIdx.x;
    const int cb = 4 * tx;      // smem col base: window cols cb..cb+5

    // ---- gather 3x6 window values + column sums (shared across 4 pixels) ----
    float v[3][6];
    float c1[6], c2[6], ct[6];
    #pragma unroll
    for (int j = 0; j < 6; j++) { c1[j] = 0.f; c2[j] = 0.f; ct[j] = 0.f; }

    #pragma unroll
    for (int i = 0; i < 3; i++) {
        const float4 a0 = *(const float4*)&xs[ty + i][cb];
        const float4 a1 = *(const float4*)&xs[ty + i][cb + 4];
        const float4 t0 = *(const float4*)&ts[ty + i][cb];
        const float4 t1 = *(const float4*)&ts[ty + i][cb + 4];
        const float rv[6] = {a0.x, a0.y, a0.z, a0.w, a1.x, a1.y};
        const float rt[6] = {t0.x, t0.y, t0.z, t0.w, t1.x, t1.y};
        #pragma unroll
        for (int j = 0; j < 6; j++) {
            v[i][j] = rv[j];
            c1[j] += rv[j];
            c2[j] = fmaf(rv[j], rv[j], c2[j]);
            ct[j] += rt[j];
        }
    }

    const float inv9 = 1.0f / 9.0f;
    const float E = 0.60653065971263342f;   // exp(-0.5)
    const float EE = 1e-6f * E;

    float4 con, en, ent, ho;
    float* conp = &con.x; float* enp = &en.x; float* entp = &ent.x; float* hop = &ho.x;

    #pragma unroll
    for (int k = 0; k < 4; k++) {
        const float s1 = c1[k] + c1[k + 1] + c1[k + 2];
        const float s2 = c2[k] + c2[k + 1] + c2[k + 2];
        const float st = ct[k] + ct[k + 1] + ct[k + 2];

        const float mean = s1 * inv9;
        float ss = fmaf(-s1, mean, s2);          // sum of squared deviations
        ss = fmaxf(ss, 0.0f);

        const float stdv = sqrtf(ss * 0.125f) + 1e-6f;   // ddof=1
        const float r = __fdividef(1.0f, stdv);
        const float contrast = ss * inv9 * r * r;

        float sa = 0.0f;
        #pragma unroll
        for (int i = 0; i < 3; i++) {
            #pragma unroll
            for (int j = 0; j < 3; j++)
                sa += fabsf(v[i][k + j] - mean);
        }
        const float homog = __fdividef(1.0f, fmaf(sa, inv9, 1.0f));

        conp[k] = fmaf(contrast, E, EE);
        enp[k]  = fmaf(s2 * inv9, E, EE);
        entp[k] = fmaf(-st * inv9, E, EE);
        hop[k]  = fmaf(homog, E, EE);
    }

    const int h = h0 + ty;
    const int w = w0 + cb;
    float4* __restrict__ o =
        (float4*)(out + (size_t)img * 4 * HW + h * 256 + w);

    o[0 * HW / 4] = con;
    o[1 * HW / 4] = en;
    o[2 * HW / 4] = ent;
    o[3 * HW / 4] = ho;
}

extern "C" void kernel_launch(void* const* d_in, const int* in_sizes, int n_in,
                              void* d_out, int out_size)
{
    const float* x = (const float*)d_in[0];
    float* out = (float*)d_out;
    (void)in_sizes; (void)n_in; (void)out_size;

    dim3 block(32, 8);
    dim3 grid(256 / TW, 256 / TH, 8 * 16);
    glcm_martingale_kernel<<<grid, block>>>(x, out);
}

// round 5
// speedup vs baseline: 1.5759x; 1.1149x over previous
#include <cuda_runtime.h>

// x: [8,16,256,256] f32  ->  out: [8,64,256,256] f32
// Features per (b,c): contrast, energy, entropy, homogeneity at out channel (b*16+c)*4+f.
// Block: 32x8 threads, each thread computes 4 horizontal pixels -> tile 128x8.

#define TW 128          // tile width in pixels
#define TH 8            // tile height
#define SWU 130         // used smem cols (w-1 .. w+128)
#define SWA 132         // allocated (float4 alignment + slack)
#define SH  10          // tile rows + halo
#define HW 65536        // 256*256

__device__ __forceinline__ float fsqrt_approx(float a) {
    float r; asm("sqrt.approx.f32 %0, %1;" : "=f"(r) : "f"(a)); return r;
}
__device__ __forceinline__ float frcp_approx(float a) {
    float r; asm("rcp.approx.f32 %0, %1;" : "=f"(r) : "f"(a)); return r;
}

__global__ __launch_bounds__(256) void glcm_martingale_kernel(
    const float* __restrict__ x, float* __restrict__ out)
{
    __shared__ float xs[SH][SWA];
    __shared__ float ts[SH][SWA];

    const int img = blockIdx.z;                 // b*16+c
    const int h0  = blockIdx.y * TH;
    const int w0  = blockIdx.x * TW;
    const float* __restrict__ xin = x + (size_t)img * HW;

    // ---- cooperative tile load: rows h0-1..h0+8, cols w0-1..w0+128 ----
    const int tid = threadIdx.y * 32 + threadIdx.x;
    for (int idx = tid; idx < SH * SWU; idx += 256) {
        const int r = idx / SWU;
        const int c = idx - r * SWU;
        const int gh = h0 - 1 + r;
        const int gw = w0 - 1 + c;
        float v = 0.0f;
        if ((unsigned)gh < 256u && (unsigned)gw < 256u)
            v = xin[gh * 256 + gw];
        xs[r][c] = v;
        ts[r][c] = v * __logf(v + 1e-6f);   // 0*log(eps) = 0 matches zero-pad
    }
    __syncthreads();

    const int ty = threadIdx.y, tx = threadIdx.x;
    const int cb = 4 * tx;      // smem col base: window cols cb..cb+5

    // ---- gather 3x6 window values + column sums (shared across 4 pixels) ----
    float v[3][6];
    float c1[6], c2[6], ct[6];
    #pragma unroll
    for (int j = 0; j < 6; j++) { c1[j] = 0.f; c2[j] = 0.f; ct[j] = 0.f; }

    #pragma unroll
    for (int i = 0; i < 3; i++) {
        const float4 a0 = *(const float4*)&xs[ty + i][cb];
        const float4 a1 = *(const float4*)&xs[ty + i][cb + 4];
        const float4 t0 = *(const float4*)&ts[ty + i][cb];
        const float4 t1 = *(const float4*)&ts[ty + i][cb + 4];
        const float rv[6] = {a0.x, a0.y, a0.z, a0.w, a1.x, a1.y};
        const float rt[6] = {t0.x, t0.y, t0.z, t0.w, t1.x, t1.y};
        #pragma unroll
        for (int j = 0; j < 6; j++) {
            v[i][j] = rv[j];
            c1[j] += rv[j];
            c2[j] = fmaf(rv[j], rv[j], c2[j]);
            ct[j] += rt[j];
        }
    }

    const float inv9 = 1.0f / 9.0f;
    const float E = 0.60653065971263342f;   // exp(-0.5)
    const float EE = 1e-6f * E;

    float4 con, en, ent, ho;
    float* conp = &con.x; float* enp = &en.x; float* entp = &ent.x; float* hop = &ho.x;

    #pragma unroll
    for (int k = 0; k < 4; k++) {
        const float s1 = c1[k] + c1[k + 1] + c1[k + 2];
        const float s2 = c2[k] + c2[k + 1] + c2[k + 2];
        const float st = ct[k] + ct[k + 1] + ct[k + 2];

        const float mean = s1 * inv9;
        float ss = fmaf(-s1, mean, s2);          // sum of squared deviations
        ss = fmaxf(ss, 0.0f);

        const float stdv = fsqrt_approx(ss * 0.125f) + 1e-6f;   // ddof=1
        const float r = frcp_approx(stdv);
        const float contrast = ss * inv9 * r * r;

        float sa = 0.0f;
        #pragma unroll
        for (int i = 0; i < 3; i++) {
            #pragma unroll
            for (int j = 0; j < 3; j++)
                sa += fabsf(v[i][k + j] - mean);
        }
        const float homog = frcp_approx(fmaf(sa, inv9, 1.0f));

        conp[k] = fmaf(contrast, E, EE);
        enp[k]  = fmaf(s2 * inv9, E, EE);
        entp[k] = fmaf(-st * inv9, E, EE);
        hop[k]  = fmaf(homog, E, EE);
    }

    const int h = h0 + ty;
    const int w = w0 + cb;
    float4* __restrict__ o =
        (float4*)(out + (size_t)img * 4 * HW + h * 256 + w);

    o[0 * HW / 4] = con;
    o[1 * HW / 4] = en;
    o[2 * HW / 4] = ent;
    o[3 * HW / 4] = ho;
}

extern "C" void kernel_launch(void* const* d_in, const int* in_sizes, int n_in,
                              void* d_out, int out_size)
{
    const float* x = (const float*)d_in[0];
    float* out = (float*)d_out;
    (void)in_sizes; (void)n_in; (void)out_size;

    dim3 block(32, 8);
    dim3 grid(256 / TW, 256 / TH, 8 * 16);
    glcm_martingale_kernel<<<grid, block>>>(x, out);
}